// round 6
// baseline (speedup 1.0000x reference)
#include <cuda_runtime.h>
#include <cuda_bf16.h>

// Problem constants
#define B_   8192
#define M_   50000
#define NU_  16
#define F_   128
#define E_   65536

#define SCATTER_BLOCKS ((E_ * 32) / 512)   // 4096

// Scratch (device globals — no allocation allowed)
__device__ float4 g_h1agg4[B_ * (F_ / 4)];   // h1_agg  [B,F]
__device__ float4 g_h2agg4[B_ * (F_ / 4)];   // h2_agg  [B,F]
__device__ int    g_winner[M_];              // winning b per V_n row (max b), -1 if untouched
__device__ float  g_ov[B_ * NU_];            // overlap[b,u]
__device__ float  g_le[B_ * NU_];            // loc_energy[b,u]

// ---------------------------------------------------------------------------
// K1: init scratch (every replay — deterministic)
// ---------------------------------------------------------------------------
__global__ void init_kernel() {
    int t = blockIdx.x * blockDim.x + threadIdx.x;
    const int NV = B_ * (F_ / 4);  // 262144
    if (t < NV) {
        g_h1agg4[t] = make_float4(0.f, 0.f, 0.f, 0.f);
        g_h2agg4[t] = make_float4(0.f, 0.f, 0.f, 0.f);
    }
    if (t < M_) g_winner[t] = -1;
}

// ---------------------------------------------------------------------------
// K2: winner resolution (last-update-wins == max b wins)
// ---------------------------------------------------------------------------
__global__ void winner_kernel(const int* __restrict__ v_idx) {
    int b = blockIdx.x * blockDim.x + threadIdx.x;
    if (b < B_) atomicMax(&g_winner[v_idx[b]], b);
}

// ---------------------------------------------------------------------------
// K3: segment sums via float4 atomics (pure)
// ---------------------------------------------------------------------------
__global__ __launch_bounds__(512)
void scatter_kernel(const float4* __restrict__ h1_4,
                    const int*    __restrict__ h1_idx,
                    const float4* __restrict__ h2_4,
                    const int*    __restrict__ h2_idx) {
    int t = blockIdx.x * 512 + threadIdx.x;      // t in [0, E*32)
    int e = t >> 5;
    int c = t & 31;
    float4 a = __ldcs(h1_4 + t);
    float4 b = __ldcs(h2_4 + t);
    int ia = __ldg(h1_idx + e) * 32 + c;
    int ib = __ldg(h2_idx + e) * 32 + c;
    atomicAdd(&g_h1agg4[ia], a);
    atomicAdd(&g_h2agg4[ib], b);
}

// ---------------------------------------------------------------------------
// KA: copy + dots. One block per V_n row.
//   non-winner row: streaming copy (identical to the 80%-DRAM pure copy).
//   winner row: compute ov/le for b=winner via warp-local shuffles
//               (no __syncthreads, no output write — deferred to K-update).
// ---------------------------------------------------------------------------
__global__ __launch_bounds__(512)
void copy_dots_kernel(const float*  __restrict__ Vn,
                      const float4* __restrict__ mo4,
                      float*        __restrict__ vout) {
    int row = blockIdx.x;
    int t   = threadIdx.x;
    int win = g_winner[row];
    float4 v = __ldcs((const float4*)(Vn + (size_t)row * (NU_ * F_)) + t);
    if (win < 0) {
        __stcs((float4*)(vout + (size_t)row * (NU_ * F_)) + t, v);
        return;
    }
    // dots for b = win; warp u holds chunk u of the row
    int u = t >> 5, c = t & 31;
    int i = win * 32 + c;
    float4 m  = __ldg(mo4 + i);
    float4 a1 = g_h1agg4[i];
    float4 a2 = g_h2agg4[i];
    // g = mo + h1_agg + h2_agg
    float4 g = make_float4(m.x + a1.x + a2.x, m.y + a1.y + a2.y,
                           m.z + a1.z + a2.z, m.w + a1.w + a2.w);
    float ov = v.x * m.x + v.y * m.y + v.z * m.z + v.w * m.w;
    float le = v.x * g.x + v.y * g.y + v.z * g.z + v.w * g.w;
    #pragma unroll
    for (int o = 16; o; o >>= 1) {
        ov += __shfl_xor_sync(0xFFFFFFFF, ov, o);
        le += __shfl_xor_sync(0xFFFFFFFF, le, o);
    }
    if (c == 0) {
        g_ov[win * NU_ + u] = ov;
        g_le[win * NU_ + u] = le;
    }
}

// ---------------------------------------------------------------------------
// KD: duplicate dots — b's that gather a row they did NOT win (~565).
//   One warp per (b,u); early-out for winners. No barriers.
// ---------------------------------------------------------------------------
__global__ __launch_bounds__(256)
void dup_dots_kernel(const int*    __restrict__ v_idx,
                     const float*  __restrict__ Vn,
                     const float4* __restrict__ mo4) {
    int w    = blockIdx.x * 8 + (threadIdx.x >> 5);  // global warp id
    int lane = threadIdx.x & 31;
    int b = w >> 4, u = w & 15;
    int row = __ldg(v_idx + b);
    if (g_winner[row] == b) return;                  // winner handled in KA
    float4 v = __ldg((const float4*)(Vn + ((size_t)row * NU_ + u) * F_) + lane);
    int i = b * 32 + lane;
    float4 m  = __ldg(mo4 + i);
    float4 a1 = g_h1agg4[i];
    float4 a2 = g_h2agg4[i];
    float4 g = make_float4(m.x + a1.x + a2.x, m.y + a1.y + a2.y,
                           m.z + a1.z + a2.z, m.w + a1.w + a2.w);
    float ov = v.x * m.x + v.y * m.y + v.z * m.z + v.w * m.w;
    float le = v.x * g.x + v.y * g.y + v.z * g.z + v.w * g.w;
    #pragma unroll
    for (int o = 16; o; o >>= 1) {
        ov += __shfl_xor_sync(0xFFFFFFFF, ov, o);
        le += __shfl_xor_sync(0xFFFFFFFF, le, o);
    }
    if (lane == 0) {
        g_ov[b * NU_ + u] = ov;
        g_le[b * NU_ + u] = le;
    }
}

// ---------------------------------------------------------------------------
// KU: per-b energy + winner-row update. One block per b (512 threads).
//   warp0: denom = gram[b]@ov, p-weights, energy.
//   winner block: re-read row, top_states = tanh(V + denom[u]*feats), write.
// ---------------------------------------------------------------------------
__global__ __launch_bounds__(512)
void update_kernel(const float4* __restrict__ mo4,
                   const float*  __restrict__ Vn,
                   const int*    __restrict__ v_idx,
                   const float*  __restrict__ gram,
                   float*        __restrict__ energy_out,
                   float*        __restrict__ vout) {
    int b    = blockIdx.x;
    int lane = threadIdx.x & 31;
    int u    = threadIdx.x >> 5;

    __shared__ float dn_s[16];

    int row = __ldg(v_idx + b);
    bool iswin = (g_winner[row] == b);

    // winner-row loads issued early (in flight during the matvec)
    float4 v, m, a1;
    if (iswin) {
        v  = __ldcs((const float4*)(Vn + (size_t)row * (NU_ * F_)) + threadIdx.x);
        int i = b * 32 + lane;
        m  = __ldg(mo4 + i);
        a1 = g_h1agg4[i];
    }

    // warp 0: denom (16x16 matvec), p-weights, energy
    if (u == 0) {
        float d = 0.f, l = 0.f;
        if (lane < 16) {
            const float* gr = gram + (size_t)b * (NU_ * NU_) + lane * NU_;
            const float* ovp = g_ov + b * NU_;
            #pragma unroll
            for (int k = 0; k < 16; k++) d += gr[k] * ovp[k];
            l = g_le[b * NU_ + lane];
        }
        float d2 = d * d;
        float ns = l * d2;   // lanes >=16 contribute 0
        float ds = d2;
        #pragma unroll
        for (int o = 16; o; o >>= 1) {
            ns += __shfl_xor_sync(0xFFFFFFFF, ns, o);
            ds += __shfl_xor_sync(0xFFFFFFFF, ds, o);
        }
        if (lane < 16) dn_s[lane] = d;
        if (lane == 0) energy_out[b] = ns / ds;
    }
    __syncthreads();

    if (iswin) {
        float  dn = dn_s[u];
        float4 t;                          // feats = mo + h1_agg
        t.x = tanhf(v.x + dn * (m.x + a1.x));
        t.y = tanhf(v.y + dn * (m.y + a1.y));
        t.z = tanhf(v.z + dn * (m.z + a1.z));
        t.w = tanhf(v.w + dn * (m.w + a1.w));
        __stcs((float4*)(vout + (size_t)row * (NU_ * F_)) + threadIdx.x, t);
    }
}

// ---------------------------------------------------------------------------
extern "C" void kernel_launch(void* const* d_in, const int* in_sizes, int n_in,
                              void* d_out, int out_size) {
    const float* mo    = (const float*)d_in[0];
    const float* Vn    = (const float*)d_in[1];
    const int*   vidx  = (const int*)  d_in[2];
    const float* h1    = (const float*)d_in[3];
    const int*   h1i   = (const int*)  d_in[4];
    const float* h2    = (const float*)d_in[5];
    const int*   h2i   = (const int*)  d_in[6];
    const float* gram  = (const float*)d_in[7];

    float* energy = (float*)d_out;        // [B]
    float* vout   = energy + B_;          // [M, NU, F]

    {   // K1: zero aggregates, winner=-1
        int n = B_ * (F_ / 4);            // 262144 (>= M_)
        init_kernel<<<(n + 511) / 512, 512>>>();
    }
    // K2: resolve winners
    winner_kernel<<<(B_ + 255) / 256, 256>>>(vidx);

    // K3: segment sums
    scatter_kernel<<<SCATTER_BLOCKS, 512>>>(
        (const float4*)h1, h1i, (const float4*)h2, h2i);

    // KA: copy all non-winner rows + dots for winner b's (one pass over V_n)
    copy_dots_kernel<<<M_, 512>>>(Vn, (const float4*)mo, vout);

    // KD: dots for duplicate (non-winner) gatherers
    dup_dots_kernel<<<(B_ * NU_) / 8, 256>>>(vidx, Vn, (const float4*)mo);

    // KU: energy + winner-row updates
    update_kernel<<<B_, 512>>>((const float4*)mo, Vn, vidx, gram, energy, vout);
}

// round 7
// speedup vs baseline: 1.2726x; 1.2726x over previous
#include <cuda_runtime.h>
#include <cuda_bf16.h>

// Problem constants
#define B_   8192
#define M_   50000
#define NU_  16
#define F_   128
#define E_   65536

#define SCATTER_BLOCKS ((E_ * 32) / 512)   // 4096

// Scratch (device globals — no allocation allowed)
__device__ float4 g_h1agg4[B_ * (F_ / 4)];   // h1_agg  [B,F]
__device__ float4 g_h2agg4[B_ * (F_ / 4)];   // h2_agg  [B,F]
__device__ int    g_winner[M_];              // winning b per V_n row (max b), -1 if untouched

// ---------------------------------------------------------------------------
// K1: init scratch (every replay — deterministic)
// ---------------------------------------------------------------------------
__global__ void init_kernel() {
    int t = blockIdx.x * blockDim.x + threadIdx.x;
    const int NV = B_ * (F_ / 4);  // 262144
    if (t < NV) {
        g_h1agg4[t] = make_float4(0.f, 0.f, 0.f, 0.f);
        g_h2agg4[t] = make_float4(0.f, 0.f, 0.f, 0.f);
    }
    if (t < M_) g_winner[t] = -1;
}

// ---------------------------------------------------------------------------
// K2: winner resolution (last-update-wins == max b wins)
// ---------------------------------------------------------------------------
__global__ void winner_kernel(const int* __restrict__ v_idx) {
    int b = blockIdx.x * blockDim.x + threadIdx.x;
    if (b < B_) atomicMax(&g_winner[v_idx[b]], b);
}

// ---------------------------------------------------------------------------
// K3: segment sums via float4 atomics
// ---------------------------------------------------------------------------
__global__ __launch_bounds__(512)
void scatter_kernel(const float4* __restrict__ h1_4,
                    const int*    __restrict__ h1_idx,
                    const float4* __restrict__ h2_4,
                    const int*    __restrict__ h2_idx) {
    int t = blockIdx.x * 512 + threadIdx.x;      // t in [0, E*32)
    int e = t >> 5;
    int c = t & 31;
    float4 a = __ldcs(h1_4 + t);
    float4 b = __ldcs(h2_4 + t);
    int ia = __ldg(h1_idx + e) * 32 + c;
    int ib = __ldg(h2_idx + e) * 32 + c;
    atomicAdd(&g_h1agg4[ia], a);
    atomicAdd(&g_h2agg4[ib], b);
}

// ---------------------------------------------------------------------------
// KA: one block per V_n row, 256 threads, 2 float4 per thread (MLP=2, R1 shape).
//   non-winner row: pure streaming copy.
//   winner row: full in-register pipeline — dots -> denom -> energy -> tanh ->
//               write updated row. Row data never re-read.
//   Thread t holds u1 = t>>5 (chunk t) and u2 = u1+8 (chunk t+256), c = t&31.
// ---------------------------------------------------------------------------
__global__ __launch_bounds__(256)
void copy_fused_kernel(const float*  __restrict__ Vn,
                       const float4* __restrict__ mo4,
                       const float*  __restrict__ gram,
                       float*        __restrict__ energy_out,
                       float*        __restrict__ vout) {
    int row = blockIdx.x;
    int t   = threadIdx.x;
    int win = g_winner[row];

    const float4* src = (const float4*)(Vn   + (size_t)row * (NU_ * F_));
    float4*       dst = (float4*)      (vout + (size_t)row * (NU_ * F_));
    float4 v1 = __ldcs(src + t);
    float4 v2 = __ldcs(src + t + 256);

    if (win < 0) {
        __stcs(dst + t,       v1);
        __stcs(dst + t + 256, v2);
        return;
    }

    // ---- winner path: b = win ----
    int w = t >> 5, c = t & 31;          // warp w handles u = w and u = w+8
    int i = win * 32 + c;
    float4 m  = __ldg(mo4 + i);
    float4 a1 = g_h1agg4[i];
    float4 a2 = g_h2agg4[i];
    float4 f  = make_float4(m.x + a1.x, m.y + a1.y, m.z + a1.z, m.w + a1.w); // feats
    float4 g  = make_float4(f.x + a2.x, f.y + a2.y, f.z + a2.z, f.w + a2.w); // feats+h2

    float ov1 = v1.x * m.x + v1.y * m.y + v1.z * m.z + v1.w * m.w;
    float le1 = v1.x * g.x + v1.y * g.y + v1.z * g.z + v1.w * g.w;
    float ov2 = v2.x * m.x + v2.y * m.y + v2.z * m.z + v2.w * m.w;
    float le2 = v2.x * g.x + v2.y * g.y + v2.z * g.z + v2.w * g.w;
    #pragma unroll
    for (int o = 16; o; o >>= 1) {
        ov1 += __shfl_xor_sync(0xFFFFFFFF, ov1, o);
        le1 += __shfl_xor_sync(0xFFFFFFFF, le1, o);
        ov2 += __shfl_xor_sync(0xFFFFFFFF, ov2, o);
        le2 += __shfl_xor_sync(0xFFFFFFFF, le2, o);
    }

    __shared__ float ov_s[16], le_s[16], dn_s[16];
    if (c == 0) {
        ov_s[w]     = ov1;  le_s[w]     = le1;
        ov_s[w + 8] = ov2;  le_s[w + 8] = le2;
    }
    __syncthreads();

    // warp 0: denom = gram[win] @ ov (16x16 matvec), p-weights, energy[win]
    if (w == 0) {
        float d = 0.f, l = 0.f;
        if (c < 16) {
            const float* gr = gram + (size_t)win * (NU_ * NU_) + c * NU_;
            #pragma unroll
            for (int k = 0; k < 16; k++) d += gr[k] * ov_s[k];
            l = le_s[c];
        }
        float d2 = d * d;
        float ns = l * d2;   // lanes >=16 contribute 0
        float ds = d2;
        #pragma unroll
        for (int o = 16; o; o >>= 1) {
            ns += __shfl_xor_sync(0xFFFFFFFF, ns, o);
            ds += __shfl_xor_sync(0xFFFFFFFF, ds, o);
        }
        if (c < 16) dn_s[c] = d;
        if (c == 0) energy_out[win] = ns / ds;
    }
    __syncthreads();

    // top_states = tanh(V + denom[u]*feats) — row still in registers
    float dn1 = dn_s[w], dn2 = dn_s[w + 8];
    float4 t1, t2;
    t1.x = tanhf(v1.x + dn1 * f.x);  t1.y = tanhf(v1.y + dn1 * f.y);
    t1.z = tanhf(v1.z + dn1 * f.z);  t1.w = tanhf(v1.w + dn1 * f.w);
    t2.x = tanhf(v2.x + dn2 * f.x);  t2.y = tanhf(v2.y + dn2 * f.y);
    t2.z = tanhf(v2.z + dn2 * f.z);  t2.w = tanhf(v2.w + dn2 * f.w);
    __stcs(dst + t,       t1);
    __stcs(dst + t + 256, t2);
}

// ---------------------------------------------------------------------------
// KD: duplicate-gatherer energies — one warp per b; exits unless b is a
//   non-winner duplicate (~565). Fully register-resident.
// ---------------------------------------------------------------------------
__global__ __launch_bounds__(256)
void dup_energy_kernel(const int*    __restrict__ v_idx,
                       const float*  __restrict__ Vn,
                       const float4* __restrict__ mo4,
                       const float*  __restrict__ gram,
                       float*        __restrict__ energy_out) {
    int b    = blockIdx.x * 8 + (threadIdx.x >> 5);
    int lane = threadIdx.x & 31;
    if (b >= B_) return;
    int row = __ldg(v_idx + b);
    if (g_winner[row] == b) return;          // energy written by KA

    int i = b * 32 + lane;
    float4 m  = __ldg(mo4 + i);
    float4 a1 = g_h1agg4[i];
    float4 a2 = g_h2agg4[i];
    float4 g  = make_float4(m.x + a1.x + a2.x, m.y + a1.y + a2.y,
                            m.z + a1.z + a2.z, m.w + a1.w + a2.w);

    float ov[16], le[16];
    const float4* vrow = (const float4*)(Vn + (size_t)row * (NU_ * F_));
    #pragma unroll
    for (int u = 0; u < 16; u++) {
        float4 v = __ldg(vrow + u * 32 + lane);
        float o1 = v.x * m.x + v.y * m.y + v.z * m.z + v.w * m.w;
        float l1 = v.x * g.x + v.y * g.y + v.z * g.z + v.w * g.w;
        #pragma unroll
        for (int o = 16; o; o >>= 1) {
            o1 += __shfl_xor_sync(0xFFFFFFFF, o1, o);
            l1 += __shfl_xor_sync(0xFFFFFFFF, l1, o);
        }
        ov[u] = o1; le[u] = l1;               // full sum in every lane
    }

    float d = 0.f, l = 0.f;
    if (lane < 16) {
        const float* gr = gram + (size_t)b * (NU_ * NU_) + lane * NU_;
        #pragma unroll
        for (int k = 0; k < 16; k++) d += gr[k] * ov[k];
        l = le[lane];
    }
    float d2 = d * d;
    float ns = l * d2;
    float ds = d2;
    #pragma unroll
    for (int o = 16; o; o >>= 1) {
        ns += __shfl_xor_sync(0xFFFFFFFF, ns, o);
        ds += __shfl_xor_sync(0xFFFFFFFF, ds, o);
    }
    if (lane == 0) energy_out[b] = ns / ds;
}

// ---------------------------------------------------------------------------
extern "C" void kernel_launch(void* const* d_in, const int* in_sizes, int n_in,
                              void* d_out, int out_size) {
    const float* mo    = (const float*)d_in[0];
    const float* Vn    = (const float*)d_in[1];
    const int*   vidx  = (const int*)  d_in[2];
    const float* h1    = (const float*)d_in[3];
    const int*   h1i   = (const int*)  d_in[4];
    const float* h2    = (const float*)d_in[5];
    const int*   h2i   = (const int*)  d_in[6];
    const float* gram  = (const float*)d_in[7];

    float* energy = (float*)d_out;        // [B]
    float* vout   = energy + B_;          // [M, NU, F]

    {   // K1: zero aggregates, winner=-1
        int n = B_ * (F_ / 4);            // 262144 (>= M_)
        init_kernel<<<(n + 511) / 512, 512>>>();
    }
    // K2: resolve winners
    winner_kernel<<<(B_ + 255) / 256, 256>>>(vidx);

    // K3: segment sums
    scatter_kernel<<<SCATTER_BLOCKS, 512>>>(
        (const float4*)h1, h1i, (const float4*)h2, h2i);

    // KA: single pass over V_n — copy + full winner pipeline
    copy_fused_kernel<<<M_, 256>>>(Vn, (const float4*)mo, gram, energy, vout);

    // KD: energies for duplicate (non-winner) gatherers
    dup_energy_kernel<<<(B_ + 7) / 8, 256>>>(vidx, Vn, (const float4*)mo, gram, energy);
}

// round 8
// speedup vs baseline: 1.2960x; 1.0184x over previous
#include <cuda_runtime.h>
#include <cuda_bf16.h>

// Problem constants
#define B_   8192
#define M_   50000
#define NU_  16
#define F_   128
#define E_   65536

#define SCATTER_BLOCKS ((E_ * 32) / 512)   // 4096
#define DUP_BLOCKS (B_ / 8)                // 1024: 8 warps/block, 1 b per warp
#define KA_GRID (M_ + DUP_BLOCKS)          // 51024

// Scratch (device globals — no allocation allowed)
__device__ float4 g_h1agg4[B_ * (F_ / 4)];   // h1_agg  [B,F]
__device__ float4 g_h2agg4[B_ * (F_ / 4)];   // h2_agg  [B,F]
__device__ int    g_winner[M_];              // winning b per V_n row (max b), -1 if untouched

// ---------------------------------------------------------------------------
// K1: init scratch (every replay — deterministic)
// ---------------------------------------------------------------------------
__global__ void init_kernel() {
    int t = blockIdx.x * blockDim.x + threadIdx.x;
    const int NV = B_ * (F_ / 4);  // 262144
    if (t < NV) {
        g_h1agg4[t] = make_float4(0.f, 0.f, 0.f, 0.f);
        g_h2agg4[t] = make_float4(0.f, 0.f, 0.f, 0.f);
    }
    if (t < M_) g_winner[t] = -1;
}

// ---------------------------------------------------------------------------
// K2: segment sums via float4 atomics + winner resolution (fused)
//   last-update-wins (XLA scatter order) == max b wins
// ---------------------------------------------------------------------------
__global__ __launch_bounds__(512)
void scatter_kernel(const float4* __restrict__ h1_4,
                    const int*    __restrict__ h1_idx,
                    const float4* __restrict__ h2_4,
                    const int*    __restrict__ h2_idx,
                    const int*    __restrict__ v_idx) {
    int t = blockIdx.x * 512 + threadIdx.x;      // t in [0, E*32)
    int e = t >> 5;
    int c = t & 31;
    float4 a = __ldcs(h1_4 + t);
    float4 b = __ldcs(h2_4 + t);
    int ia = __ldg(h1_idx + e) * 32 + c;
    int ib = __ldg(h2_idx + e) * 32 + c;
    atomicAdd(&g_h1agg4[ia], a);
    atomicAdd(&g_h2agg4[ib], b);
    if (t < B_) atomicMax(&g_winner[__ldg(v_idx + t)], t);
}

// ---------------------------------------------------------------------------
// KA: one kernel, two block flavors.
//   bid <  M_ : per-row copy (256 thr, 2 float4 each, MLP=2);
//               winner rows run the full in-register pipeline:
//               dots -> gram matvec -> energy -> tanh -> write updated row.
//   bid >= M_ : dup-energy blocks — 8 warps, warp w handles b = (bid-M_)*8+w;
//               exits unless b gathers a row it did NOT win (~565 active).
//               Sequential-v accumulation keeps register count low.
// ---------------------------------------------------------------------------
__global__ __launch_bounds__(256)
void fused_kernel(const float*  __restrict__ Vn,
                  const float4* __restrict__ mo4,
                  const float*  __restrict__ gram,
                  const int*    __restrict__ v_idx,
                  float*        __restrict__ energy_out,
                  float*        __restrict__ vout) {
    int bid = blockIdx.x;

    if (bid >= M_) {
        // ---------------- dup-energy tail blocks ----------------
        int lane = threadIdx.x & 31;
        int b = (bid - M_) * 8 + (threadIdx.x >> 5);
        int row = __ldg(v_idx + b);
        if (g_winner[row] == b) return;      // winner's energy written below

        int i = b * 32 + lane;
        float4 m  = __ldg(mo4 + i);
        float4 a1 = g_h1agg4[i];
        float4 a2 = g_h2agg4[i];
        float4 g  = make_float4(m.x + a1.x + a2.x, m.y + a1.y + a2.y,
                                m.z + a1.z + a2.z, m.w + a1.w + a2.w);

        const float4* vrow = (const float4*)(Vn + (size_t)row * (NU_ * F_));
        const float*  gr   = gram + (size_t)b * (NU_ * NU_);
        float d = 0.f, l = 0.f;              // lane u (<16): denom_u, le_u
        #pragma unroll
        for (int u = 0; u < 16; u++) {
            float4 v = __ldg(vrow + u * 32 + lane);
            float o1 = v.x * m.x + v.y * m.y + v.z * m.z + v.w * m.w;
            float l1 = v.x * g.x + v.y * g.y + v.z * g.z + v.w * g.w;
            #pragma unroll
            for (int o = 16; o; o >>= 1) {
                o1 += __shfl_xor_sync(0xFFFFFFFF, o1, o);
                l1 += __shfl_xor_sync(0xFFFFFFFF, l1, o);
            }
            if (lane < 16) d += gr[lane * NU_ + u] * o1;
            if (lane == u) l = l1;
        }
        float d2 = d * d;
        float ns = (lane < 16) ? l * d2 : 0.f;
        float ds = (lane < 16) ? d2 : 0.f;
        #pragma unroll
        for (int o = 16; o; o >>= 1) {
            ns += __shfl_xor_sync(0xFFFFFFFF, ns, o);
            ds += __shfl_xor_sync(0xFFFFFFFF, ds, o);
        }
        if (lane == 0) energy_out[b] = ns / ds;
        return;
    }

    // ---------------- copy / winner blocks ----------------
    int row = bid;
    int t   = threadIdx.x;
    int win = g_winner[row];

    const float4* src = (const float4*)(Vn   + (size_t)row * (NU_ * F_));
    float4*       dst = (float4*)      (vout + (size_t)row * (NU_ * F_));
    float4 v1 = __ldcs(src + t);
    float4 v2 = __ldcs(src + t + 256);

    if (win < 0) {
        __stcs(dst + t,       v1);
        __stcs(dst + t + 256, v2);
        return;
    }

    // winner path: b = win; warp w handles u = w and u = w+8
    int w = t >> 5, c = t & 31;
    int i = win * 32 + c;
    float4 m  = __ldg(mo4 + i);
    float4 a1 = g_h1agg4[i];
    float4 a2 = g_h2agg4[i];
    float4 f  = make_float4(m.x + a1.x, m.y + a1.y, m.z + a1.z, m.w + a1.w); // feats
    float4 g  = make_float4(f.x + a2.x, f.y + a2.y, f.z + a2.z, f.w + a2.w); // feats+h2

    float ov1 = v1.x * m.x + v1.y * m.y + v1.z * m.z + v1.w * m.w;
    float le1 = v1.x * g.x + v1.y * g.y + v1.z * g.z + v1.w * g.w;
    float ov2 = v2.x * m.x + v2.y * m.y + v2.z * m.z + v2.w * m.w;
    float le2 = v2.x * g.x + v2.y * g.y + v2.z * g.z + v2.w * g.w;
    #pragma unroll
    for (int o = 16; o; o >>= 1) {
        ov1 += __shfl_xor_sync(0xFFFFFFFF, ov1, o);
        le1 += __shfl_xor_sync(0xFFFFFFFF, le1, o);
        ov2 += __shfl_xor_sync(0xFFFFFFFF, ov2, o);
        le2 += __shfl_xor_sync(0xFFFFFFFF, le2, o);
    }

    __shared__ float ov_s[16], le_s[16], dn_s[16];
    if (c == 0) {
        ov_s[w]     = ov1;  le_s[w]     = le1;
        ov_s[w + 8] = ov2;  le_s[w + 8] = le2;
    }
    __syncthreads();

    // warp 0: denom = gram[win] @ ov, p-weights, energy[win]
    if (w == 0) {
        float d = 0.f, l = 0.f;
        if (c < 16) {
            const float* gr = gram + (size_t)win * (NU_ * NU_) + c * NU_;
            #pragma unroll
            for (int k = 0; k < 16; k++) d += gr[k] * ov_s[k];
            l = le_s[c];
        }
        float d2 = d * d;
        float ns = l * d2;   // lanes >=16 contribute 0
        float ds = d2;
        #pragma unroll
        for (int o = 16; o; o >>= 1) {
            ns += __shfl_xor_sync(0xFFFFFFFF, ns, o);
            ds += __shfl_xor_sync(0xFFFFFFFF, ds, o);
        }
        if (c < 16) dn_s[c] = d;
        if (c == 0) energy_out[win] = ns / ds;
    }
    __syncthreads();

    // top_states = tanh(V + denom[u]*feats) — row still in registers
    float dn1 = dn_s[w], dn2 = dn_s[w + 8];
    float4 t1, t2;
    t1.x = tanhf(v1.x + dn1 * f.x);  t1.y = tanhf(v1.y + dn1 * f.y);
    t1.z = tanhf(v1.z + dn1 * f.z);  t1.w = tanhf(v1.w + dn1 * f.w);
    t2.x = tanhf(v2.x + dn2 * f.x);  t2.y = tanhf(v2.y + dn2 * f.y);
    t2.z = tanhf(v2.z + dn2 * f.z);  t2.w = tanhf(v2.w + dn2 * f.w);
    __stcs(dst + t,       t1);
    __stcs(dst + t + 256, t2);
}

// ---------------------------------------------------------------------------
extern "C" void kernel_launch(void* const* d_in, const int* in_sizes, int n_in,
                              void* d_out, int out_size) {
    const float* mo    = (const float*)d_in[0];
    const float* Vn    = (const float*)d_in[1];
    const int*   vidx  = (const int*)  d_in[2];
    const float* h1    = (const float*)d_in[3];
    const int*   h1i   = (const int*)  d_in[4];
    const float* h2    = (const float*)d_in[5];
    const int*   h2i   = (const int*)  d_in[6];
    const float* gram  = (const float*)d_in[7];

    float* energy = (float*)d_out;        // [B]
    float* vout   = energy + B_;          // [M, NU, F]

    {   // K1: zero aggregates, winner=-1
        int n = B_ * (F_ / 4);            // 262144 (>= M_)
        init_kernel<<<(n + 511) / 512, 512>>>();
    }
    // K2: segment sums + winner resolution
    scatter_kernel<<<SCATTER_BLOCKS, 512>>>(
        (const float4*)h1, h1i, (const float4*)h2, h2i, vidx);

    // KA: copy + winner pipeline + dup-energy tail (single pass over V_n)
    fused_kernel<<<KA_GRID, 256>>>(Vn, (const float4*)mo, gram, vidx, energy, vout);
}